// round 11
// baseline (speedup 1.0000x reference)
#include <cuda_runtime.h>
#include <math.h>

#define NFEAT   2000
#define TOTCAND 13280
#define MAXHW   (1024*1024)
#define LVS     (2*MAXHW)
#define EPSF    1e-8f
#define CANDCAP 4096
#define SORTN   4096

// ---------------- static device scratch ----------------
__device__ float g_gk[5][32];
__device__ float g_lv[5][LVS];
__device__ float g_tmp[LVS];
__device__ float g_resp[5][LVS];
__device__ float g_e[5][LVS];
__device__ float g_vals[5][LVS];

__device__ unsigned g_bins[2][256];
__device__ unsigned g_prefix[2];
__device__ unsigned g_kremain[2];
__device__ unsigned g_thresh[2];
__device__ unsigned g_candcnt[2];
__device__ unsigned g_candlist[2][CANDCAP];
__device__ unsigned g_selidx[2][NFEAT];
__device__ float    g_selval[2][NFEAT];
__device__ float    g_cand_resp[2][TOTCAND];
__device__ float    g_cand_laf[2][TOTCAND][6];
__device__ unsigned g_finidx[2][NFEAT];
__device__ float    g_finval[2][NFEAT];

// Hessian kernels (reference _K2 / abs-sum: /64, /36, /64; f32-exact constants)
__constant__ float cGXX[25] = {
 -1.f/64,0.f,2.f/64,0.f,-1.f/64, -4.f/64,0.f,8.f/64,0.f,-4.f/64,
 -6.f/64,0.f,12.f/64,0.f,-6.f/64, -4.f/64,0.f,8.f/64,0.f,-4.f/64,
 -1.f/64,0.f,2.f/64,0.f,-1.f/64 };
__constant__ float cGXY[25] = {
 (float)(-1.0/36),(float)(-2.0/36),0.f,(float)(2.0/36),(float)(1.0/36),
 (float)(-2.0/36),(float)(-4.0/36),0.f,(float)(4.0/36),(float)(2.0/36),
 0.f,0.f,0.f,0.f,0.f,
 (float)(2.0/36),(float)(4.0/36),0.f,(float)(-4.0/36),(float)(-2.0/36),
 (float)(1.0/36),(float)(2.0/36),0.f,(float)(-2.0/36),(float)(-1.0/36) };
__constant__ float cGYY[25] = {     // _GXX.T
 -1.f/64,-4.f/64,-6.f/64,-4.f/64,-1.f/64, 0.f,0.f,0.f,0.f,0.f,
 2.f/64,8.f/64,12.f/64,8.f/64,2.f/64, 0.f,0.f,0.f,0.f,0.f,
 -1.f/64,-4.f/64,-6.f/64,-4.f/64,-1.f/64 };

// XLA-CPU inline exp (llvm_ir_runtime GenerateVF32Exp == Cephes expf):
// every mul/add UNFUSED, exactly as the emitted LLVM IR.
__device__ __forceinline__ float xla_expf(float input){
  float x = fminf(input, 88.3762626647950f);
  x = fmaxf(x, -88.3762626647949f);
  float fx = floorf(__fadd_rn(__fmul_rn(x, 1.44269504088896341f), 0.5f));
  float tmp = __fmul_rn(fx, 0.693359375f);
  float z   = __fmul_rn(fx, -2.12194440e-4f);
  x = __fsub_rn(x, tmp);
  x = __fsub_rn(x, z);
  float z2 = __fmul_rn(x, x);
  float y = 1.9875691500E-4f;
  y = __fadd_rn(__fmul_rn(y, x), 1.3981999507E-3f);
  y = __fadd_rn(__fmul_rn(y, x), 8.3334519073E-3f);
  y = __fadd_rn(__fmul_rn(y, x), 4.1665795894E-2f);
  y = __fadd_rn(__fmul_rn(y, x), 1.6666665459E-1f);
  y = __fadd_rn(__fmul_rn(y, x), 5.0000001201E-1f);
  y = __fadd_rn(__fmul_rn(y, z2), x);
  y = __fadd_rn(y, 1.0f);
  int n = (int)fx;
  float p2n = __uint_as_float((unsigned)(n + 127) << 23);
  return __fmul_rn(y, p2n);
}

// descending-sortable key; +-0 unified so top_k tie-break (lower idx) holds
__device__ __forceinline__ unsigned fkey(float f){
  unsigned u = __float_as_uint(f);
  if ((u << 1) == 0u) return 0x80000000u;
  return (u & 0x80000000u) ? ~u : (u | 0x80000000u);
}

__device__ __forceinline__ float cand_val(int mode, int b, unsigned i, int HW){
  if (mode == 0){
    unsigned d = i / (unsigned)HW;
    return g_vals[d][(unsigned)b*HW + (i - d*(unsigned)HW)];
  }
  return g_cand_resp[b][i];
}

// ---------------- kernels ----------------
// numpy-exact weights: f32 exp arg, ~CR exp (glibc expf), numpy pairwise_sum.
__global__ void k_initg(double a0,double a1,double a2,double a3,double a4,
                        int n0,int n1,int n2,int n3,int n4){
  int t = threadIdx.x; if (t >= 5) return;
  double sg = t==0?a0:t==1?a1:t==2?a2:t==3?a3:a4;
  int n = t==0?n0:t==1?n1:t==2?n2:t==3?n3:n4;
  int h = n/2;
  float den2 = (float)(2.0*sg*sg);
  float w[32];
  for (int i=0;i<n;i++){
    float x = (float)(i - h);
    float arg = __fdiv_rn(-(x*x), den2);
    w[i] = (float)exp((double)arg);
  }
  float r[8];
  #pragma unroll
  for (int j=0;j<8;j++) r[j] = w[j];
  int i = 8;
  for (; i + 8 <= n; i += 8){
    #pragma unroll
    for (int j=0;j<8;j++) r[j] = __fadd_rn(r[j], w[i+j]);
  }
  float sum = __fadd_rn(__fadd_rn(__fadd_rn(r[0],r[1]),__fadd_rn(r[2],r[3])),
                        __fadd_rn(__fadd_rn(r[4],r[5]),__fadd_rn(r[6],r[7])));
  for (; i < n; i++) sum = __fadd_rn(sum, w[i]);
  for (int k=0;k<n;k++) g_gk[t][k] = __fdiv_rn(w[k], sum);
}

// 1D conv, XLA naive emitter: UNFUSED mul+add, ascending taps
__global__ void k_blurv(const float* __restrict__ src, float* __restrict__ dst,
                        int H,int W,int ki,int n){
  int idx = blockIdx.x*blockDim.x + threadIdx.x;
  int HW = H*W, tot = 2*HW; if (idx >= tot) return;
  int b = idx/HW, rem = idx-b*HW;
  int y = rem/W, x = rem-(rem/W)*W;
  int p = n/2;
  const float* s = src + b*HW;
  float acc = 0.f;
  for (int i=0;i<n;i++){
    int t = y+i-p;
    t = (t<0) ? -t : ((t>=H) ? (2*H-2-t) : t);
    acc = __fadd_rn(acc, __fmul_rn(g_gk[ki][i], s[t*W+x]));
  }
  dst[idx] = acc;
}

__global__ void k_blurh(const float* __restrict__ src, float* __restrict__ dst,
                        int H,int W,int ki,int n){
  int idx = blockIdx.x*blockDim.x + threadIdx.x;
  int HW = H*W, tot = 2*HW; if (idx >= tot) return;
  int b = idx/HW, rem = idx-b*HW;
  int y = rem/W, x = rem-(rem/W)*W;
  int p = n/2;
  const float* s = src + b*HW + y*W;
  float acc = 0.f;
  for (int i=0;i<n;i++){
    int t = x+i-p;
    t = (t<0) ? -t : ((t>=W) ? (2*W-2-t) : t);
    acc = __fadd_rn(acc, __fmul_rn(g_gk[ki][i], s[t]));
  }
  dst[idx] = acc;
}

__global__ void k_down(int S){
  int idx = blockIdx.x*blockDim.x + threadIdx.x;
  int HW = S*S, tot = 2*HW; if (idx >= tot) return;
  int b = idx/HW, rem = idx-b*HW;
  int y = rem/S, x = rem-(rem/S)*S;
  int S2 = 2*S, HW2 = 4*HW;
  g_lv[0][idx] = g_lv[3][b*HW2 + (2*y)*S2 + 2*x];
}

// 2D conv, XLA naive emitter: kh OUTER, kw inner, UNFUSED mul+add
__global__ void k_hess(int H,int W,float q0,float q1,float q2,float q3,float q4){
  int l = blockIdx.y;
  int idx = blockIdx.x*blockDim.x + threadIdx.x;
  int HW = H*W, tot = 2*HW; if (idx >= tot) return;
  int b = idx/HW, rem = idx-b*HW;
  int y = rem/W, x = rem-(rem/W)*W;
  const float* s = &g_lv[l][b*HW];
  float dxx=0.f,dxy=0.f,dyy=0.f;
  #pragma unroll
  for (int i=0;i<5;i++){              // kh outer
    int yy = y+i-2; yy = yy<0?0:(yy>H-1?H-1:yy);
    #pragma unroll
    for (int j=0;j<5;j++){            // kw inner
      int xx = x+j-2; xx = xx<0?0:(xx>W-1?W-1:xx);
      float pv = s[yy*W+xx];
      dxx = __fadd_rn(dxx, __fmul_rn(cGXX[i*5+j], pv));
      dxy = __fadd_rn(dxy, __fmul_rn(cGXY[i*5+j], pv));
      dyy = __fadd_rn(dyy, __fmul_rn(cGYY[i*5+j], pv));
    }
  }
  float s4 = (l==0)?q0:(l==1)?q1:(l==2)?q2:(l==3)?q3:q4;
  float det = __fsub_rn(__fmul_rn(dxx,dyy), __fmul_rn(dxy,dxy));
  g_resp[l][idx] = __fmul_rn(det, s4);
}

__global__ void k_emap(int H,int W){
  int l = blockIdx.y;
  int idx = blockIdx.x*blockDim.x + threadIdx.x;
  int HW = H*W, tot = 2*HW; if (idx >= tot) return;
  int b = idx/HW, rem = idx-b*HW;
  int y = rem/W, x = rem-(rem/W)*W;
  float m = -3.402823466e38f;
  for (int dd=l-1; dd<=l+1; dd++){
    if (dd<0 || dd>4) continue;
    const float* r = &g_resp[dd][b*HW];
    for (int yy=y-1; yy<=y+1; yy++){
      if ((unsigned)yy >= (unsigned)H) continue;
      for (int xx=x-1; xx<=x+1; xx++){
        if ((unsigned)xx >= (unsigned)W) continue;
        m = fmaxf(m, r[yy*W+xx]);
      }
    }
  }
  g_e[l][idx] = xla_expf(__fsub_rn(g_resp[l][idx], m));
}

// reduce_window: row-major (d outer, h, w inner), UNFUSED product for num
__global__ void k_vals(int H,int W){
  int l = blockIdx.y;
  int idx = blockIdx.x*blockDim.x + threadIdx.x;
  int HW = H*W, tot = 2*HW; if (idx >= tot) return;
  int b = idx/HW, rem = idx-b*HW;
  int y = rem/W, x = rem-(rem/W)*W;
  float den=0.f, num=0.f;
  for (int dd=l-1; dd<=l+1; dd++){
    if (dd<0 || dd>4) continue;
    const float* e = &g_e[dd][b*HW];
    const float* r = &g_resp[dd][b*HW];
    for (int yy=y-1; yy<=y+1; yy++){
      if ((unsigned)yy >= (unsigned)H) continue;
      for (int xx=x-1; xx<=x+1; xx++){
        if ((unsigned)xx >= (unsigned)W) continue;
        float ev = e[yy*W+xx];
        den = __fadd_rn(den, ev);
        num = __fadd_rn(num, __fmul_rn(ev, r[yy*W+xx]));
      }
    }
  }
  g_vals[l][idx] = __fdiv_rn(num, __fadd_rn(den, EPSF));
}

__global__ void k_tkinit(){
  int t = threadIdx.x;
  if (t < 2){ g_prefix[t]=0u; g_kremain[t]=NFEAT; g_candcnt[t]=0u; }
  for (int i=t;i<512;i+=blockDim.x) ((unsigned*)g_bins)[i]=0u;
}

__global__ void k_hist(int mode,int N,int HW,int r){
  __shared__ unsigned sh[256];
  int b = blockIdx.y;
  for (int i=threadIdx.x;i<256;i+=blockDim.x) sh[i]=0u;
  __syncthreads();
  unsigned pref = g_prefix[b];
  int shift = 24 - 8*r;
  for (int i=blockIdx.x*blockDim.x+threadIdx.x; i<N; i+=gridDim.x*blockDim.x){
    unsigned key = fkey(cand_val(mode,b,(unsigned)i,HW));
    bool ok = (r==0) || ((key >> (8*(4-r))) == pref);
    if (ok) atomicAdd(&sh[(key>>shift)&0xFFu], 1u);
  }
  __syncthreads();
  for (int i=threadIdx.x;i<256;i+=blockDim.x)
    if (sh[i]) atomicAdd(&g_bins[b][i], sh[i]);
}

__global__ void k_scan(){
  int b = threadIdx.x; if (b >= 2) return;
  unsigned k = g_kremain[b];
  unsigned cum = 0; int dsel = 0;
  for (int d=255; d>=0; d--){
    unsigned c = g_bins[b][d];
    if (cum + c >= k){ dsel = d; break; }
    cum += c;
  }
  g_prefix[b] = (g_prefix[b]<<8) | (unsigned)dsel;
  g_kremain[b] = k - cum;
  g_thresh[b] = g_prefix[b];
  for (int t=0;t<256;t++) g_bins[b][t]=0u;
}

__global__ void k_compact(int mode,int N,int HW){
  int b = blockIdx.y;
  unsigned T = g_thresh[b];
  for (int i=blockIdx.x*blockDim.x+threadIdx.x; i<N; i+=gridDim.x*blockDim.x){
    unsigned key = fkey(cand_val(mode,b,(unsigned)i,HW));
    if (key >= T){
      unsigned p = atomicAdd(&g_candcnt[b], 1u);
      if (p < CANDCAP) g_candlist[b][p] = (unsigned)i;
    }
  }
}

__global__ void k_sortsel(int mode,int HW,int outmode){
  __shared__ unsigned long long s[SORTN];
  int b = blockIdx.x;
  unsigned M = g_candcnt[b]; if (M > CANDCAP) M = CANDCAP;
  for (int t=threadIdx.x; t<SORTN; t+=blockDim.x){
    unsigned long long kv = 0ULL;
    if (t < (int)M){
      unsigned i = g_candlist[b][t];
      kv = ((unsigned long long)fkey(cand_val(mode,b,i,HW)) << 32) | (unsigned)(~i);
    }
    s[t] = kv;
  }
  __syncthreads();
  for (int k=2; k<=SORTN; k<<=1){
    for (int j=k>>1; j>0; j>>=1){
      for (int i=threadIdx.x; i<SORTN; i+=blockDim.x){
        int p = i ^ j;
        if (p > i){
          unsigned long long a=s[i], c=s[p];
          bool up = ((i & k) == 0);
          if (up ? (a < c) : (a > c)){ s[i]=c; s[p]=a; }
        }
      }
      __syncthreads();
    }
  }
  for (int t=threadIdx.x; t<NFEAT; t+=blockDim.x){
    unsigned i = ~((unsigned)(s[t] & 0xFFFFFFFFULL));
    float v = cand_val(mode,b,i,HW);
    if (outmode==0){ g_selidx[b][t]=i; g_selval[b][t]=v; }
    else           { g_finidx[b][t]=i; g_finval[b][t]=v; }
  }
}

__global__ void k_laf(int H,int W,int count,int use_sel,int base){
  int j = blockIdx.x*blockDim.x + threadIdx.x;
  int b = blockIdx.y;
  if (j >= count) return;
  int HW = H*W;
  unsigned idx; float v;
  if (use_sel){ idx = g_selidx[b][j]; v = g_selval[b][j]; }
  else {
    idx = (unsigned)j;
    unsigned d0 = idx/(unsigned)HW;
    v = g_vals[d0][(unsigned)b*HW + (idx - d0*(unsigned)HW)];
  }
  int d = idx/HW, rem = idx-d*HW;
  int y = rem/W, x = rem-(rem/W)*W;
  // den: reduce_window (d,h,w); sd/sx/sy: naive 3D conv (kd,kh,kw) —
  // same nest order; all UNFUSED mul+add; zero-weight taps are exact no-ops
  float den=0.f, sd=0.f, sx=0.f, sy=0.f;
  for (int dd=d-1; dd<=d+1; dd++){
    if (dd<0 || dd>4) continue;
    const float* e = &g_e[dd][b*HW];
    for (int yy=y-1; yy<=y+1; yy++){
      if ((unsigned)yy >= (unsigned)H) continue;
      for (int xx=x-1; xx<=x+1; xx++){
        if ((unsigned)xx >= (unsigned)W) continue;
        float ev = e[yy*W+xx];
        den = __fadd_rn(den, ev);
        if (dd != d) sd = __fadd_rn(sd, __fmul_rn(ev, (float)(dd-d)));
        if (xx != x) sx = __fadd_rn(sx, __fmul_rn(ev, (float)(xx-x)));
        if (yy != y) sy = __fadd_rn(sy, __fmul_rn(ev, (float)(yy-y)));
      }
    }
  }
  float dE = __fadd_rn(den, EPSF);
  float cd = __fadd_rn(__fdiv_rn(sd,dE), (float)d);
  float cx = __fadd_rn(__fdiv_rn(sx,dE), (float)x);
  float cy = __fadd_rn(__fdiv_rn(sy,dE), (float)y);
  // pow(2,q) -> glibc powf (CR for practical purposes) == f64 exp2 rounded
  float scale = __fmul_rn(1.6f, (float)exp2((double)__fdiv_rn(cd, 3.0f)));
  float s6 = __fmul_rn(6.0f, scale);
  float g = ((__fsub_rn(cx,s6) > 0.f) && (__fadd_rn(cx,s6) < (float)(W-1)) &&
             (__fsub_rn(cy,s6) > 0.f) && (__fadd_rn(cy,s6) < (float)(H-1))) ? 1.f : 0.f;
  float mn = (float)(H < W ? H : W);
  int o = base + j;
  g_cand_resp[b][o] = __fmul_rn(v, g);
  float* Lf = g_cand_laf[b][o];
  Lf[0] = __fdiv_rn(s6,mn); Lf[1] = 0.f; Lf[2] = __fdiv_rn(cx,(float)W);
  Lf[3] = 0.f;              Lf[4] = __fdiv_rn(s6,mn); Lf[5] = __fdiv_rn(cy,(float)H);
}

__global__ void k_out(float* __restrict__ out){
  int t = blockIdx.x*blockDim.x + threadIdx.x;
  if (t >= 2*NFEAT) return;
  int b = t/NFEAT, j = t-b*NFEAT;
  unsigned i = g_finidx[b][j];
  const float* L = g_cand_laf[b][i];
  float* o = out + (b*NFEAT + j)*6;
  #pragma unroll
  for (int e=0;e<6;e++) o[e] = __fmul_rn(L[e], 1024.0f);   // exact (x2^10)
  out[2*NFEAT*6 + b*NFEAT + j] = g_finval[b][j];
}

// ---------------- host ----------------
extern "C" void kernel_launch(void* const* d_in, const int* in_sizes, int n_in,
                              void* d_out, int out_size){
  (void)in_sizes; (void)n_in; (void)out_size;
  const float* img = (const float*)d_in[0];
  float* out = (float*)d_out;

  float *p_lv = 0, *p_tmp = 0;
  cudaGetSymbolAddress((void**)&p_lv, g_lv);
  cudaGetSymbolAddress((void**)&p_tmp, g_tmp);

  double step = pow(2.0, 1.0/3.0);
  double q = sqrt(step*step - 1.0);
  double sgm[5]; int ksz[5];
  sgm[0] = sqrt(1.6*1.6 - 0.25);
  // reference recurrence: sigma_i = cs_{i-1} * q ;  cs_i = cs_{i-1} * step
  {
    double cs = 1.6;
    for (int i=1;i<5;i++){
      sgm[i] = cs * q;
      cs *= step;
    }
  }
  for (int i=0;i<5;i++){ int k=(int)(8.0*sgm[i]+1.0); if(!(k&1))k++; ksz[i]=k; }
  // sigma^4: numpy f32 ** 4 -> glibc powf (same container libm)
  float s4[5];
  {
    double cs = 1.6;
    for (int l=0;l<5;l++){
      float sgf = (float)cs;
      s4[l] = powf(sgf, 4.0f);
      cs *= step;
    }
  }

  k_initg<<<1,8>>>(sgm[0],sgm[1],sgm[2],sgm[3],sgm[4],
                   ksz[0],ksz[1],ksz[2],ksz[3],ksz[4]);

  static const int SS[7] = {1024,512,256,128,64,32,16};
  int base = 0;
  for (int o=0;o<7;o++){
    int S = SS[o], HW = S*S, tot = 2*HW;
    int thr = 256, blk = (tot+thr-1)/thr;
    if (o == 0){
      k_blurv<<<blk,thr>>>(img, p_tmp, S,S,0,ksz[0]);
      k_blurh<<<blk,thr>>>(p_tmp, p_lv, S,S,0,ksz[0]);
    } else {
      k_down<<<blk,thr>>>(S);
    }
    for (int i=1;i<5;i++){
      k_blurv<<<blk,thr>>>(p_lv+(i-1)*LVS, p_tmp, S,S,i,ksz[i]);
      k_blurh<<<blk,thr>>>(p_tmp, p_lv+i*LVS, S,S,i,ksz[i]);
    }
    dim3 g5(blk,5);
    k_hess<<<g5,thr>>>(S,S,s4[0],s4[1],s4[2],s4[3],s4[4]);
    k_emap<<<g5,thr>>>(S,S);
    k_vals<<<g5,thr>>>(S,S);

    int N = 5*HW;
    if (N > NFEAT){
      k_tkinit<<<1,256>>>();
      int hb = (N+255)/256; if (hb > 2048) hb = 2048;
      for (int r=0;r<4;r++){
        k_hist<<<dim3(hb,2),256>>>(0,N,HW,r);
        k_scan<<<1,2>>>();
      }
      k_compact<<<dim3(hb,2),256>>>(0,N,HW);
      k_sortsel<<<2,512>>>(0,HW,0);
      k_laf<<<dim3((NFEAT+127)/128,2),128>>>(S,S,NFEAT,1,base);
      base += NFEAT;
    } else {
      k_laf<<<dim3((N+127)/128,2),128>>>(S,S,N,0,base);
      base += N;
    }
  }

  // final selection over all candidates (base == 13280)
  int N = base;
  k_tkinit<<<1,256>>>();
  int hb = (N+255)/256;
  for (int r=0;r<4;r++){
    k_hist<<<dim3(hb,2),256>>>(1,N,0,r);
    k_scan<<<1,2>>>();
  }
  k_compact<<<dim3(hb,2),256>>>(1,N,0);
  k_sortsel<<<2,512>>>(1,0,1);
  k_out<<<(2*NFEAT+255)/256,256>>>(out);
}

// round 12
// speedup vs baseline: 1.1105x; 1.1105x over previous
#include <cuda_runtime.h>
#include <math.h>

#define NFEAT   2000
#define TOTCAND 13280
#define MAXHW   (1024*1024)
#define LVS     (2*MAXHW)
#define EPSF    1e-8f
#define CANDCAP 4096
#define SORTN   4096
#define C1CAP   262144
#define BX 32
#define BY 8

// ---------------- static device scratch ----------------
__device__ float g_lv[5][LVS];
__device__ float g_tmp[LVS];
__device__ float g_resp[5][LVS];
__device__ float g_e[5][LVS];
__device__ float g_vals[5][LVS];

__device__ unsigned g_bins[2][256];
__device__ unsigned g_prefix[2];
__device__ unsigned g_kremain[2];
__device__ unsigned g_thresh[2];
__device__ unsigned g_candcnt[2];
__device__ unsigned g_cnt1[2];
__device__ unsigned g_cand1[2][C1CAP];
__device__ unsigned g_candlist[2][CANDCAP];
__device__ unsigned g_selidx[2][NFEAT];
__device__ float    g_selval[2][NFEAT];
__device__ float    g_cand_resp[2][TOTCAND];
__device__ float    g_cand_laf[2][TOTCAND][6];
__device__ unsigned g_finidx[2][NFEAT];
__device__ float    g_finval[2][NFEAT];

struct KW { float w[24]; };   // blur weights passed by value (const bank)

// Hessian kernels (reference _K2 / abs-sum: /64, /36, /64; f32-exact constants)
__constant__ float cGXX[25] = {
 -1.f/64,0.f,2.f/64,0.f,-1.f/64, -4.f/64,0.f,8.f/64,0.f,-4.f/64,
 -6.f/64,0.f,12.f/64,0.f,-6.f/64, -4.f/64,0.f,8.f/64,0.f,-4.f/64,
 -1.f/64,0.f,2.f/64,0.f,-1.f/64 };
__constant__ float cGXY[25] = {
 (float)(-1.0/36),(float)(-2.0/36),0.f,(float)(2.0/36),(float)(1.0/36),
 (float)(-2.0/36),(float)(-4.0/36),0.f,(float)(4.0/36),(float)(2.0/36),
 0.f,0.f,0.f,0.f,0.f,
 (float)(2.0/36),(float)(4.0/36),0.f,(float)(-4.0/36),(float)(-2.0/36),
 (float)(1.0/36),(float)(2.0/36),0.f,(float)(-2.0/36),(float)(-1.0/36) };
__constant__ float cGYY[25] = {     // _GXX.T
 -1.f/64,-4.f/64,-6.f/64,-4.f/64,-1.f/64, 0.f,0.f,0.f,0.f,0.f,
 2.f/64,8.f/64,12.f/64,8.f/64,2.f/64, 0.f,0.f,0.f,0.f,0.f,
 -1.f/64,-4.f/64,-6.f/64,-4.f/64,-1.f/64 };

// XLA-CPU inline exp (Cephes), every mul/add UNFUSED — bit-exact vs R11
__device__ __forceinline__ float xla_expf(float input){
  float x = fminf(input, 88.3762626647950f);
  x = fmaxf(x, -88.3762626647949f);
  float fx = floorf(__fadd_rn(__fmul_rn(x, 1.44269504088896341f), 0.5f));
  float tmp = __fmul_rn(fx, 0.693359375f);
  float z   = __fmul_rn(fx, -2.12194440e-4f);
  x = __fsub_rn(x, tmp);
  x = __fsub_rn(x, z);
  float z2 = __fmul_rn(x, x);
  float y = 1.9875691500E-4f;
  y = __fadd_rn(__fmul_rn(y, x), 1.3981999507E-3f);
  y = __fadd_rn(__fmul_rn(y, x), 8.3334519073E-3f);
  y = __fadd_rn(__fmul_rn(y, x), 4.1665795894E-2f);
  y = __fadd_rn(__fmul_rn(y, x), 1.6666665459E-1f);
  y = __fadd_rn(__fmul_rn(y, x), 5.0000001201E-1f);
  y = __fadd_rn(__fmul_rn(y, z2), x);
  y = __fadd_rn(y, 1.0f);
  int n = (int)fx;
  float p2n = __uint_as_float((unsigned)(n + 127) << 23);
  return __fmul_rn(y, p2n);
}

__device__ __forceinline__ unsigned fkey(float f){
  unsigned u = __float_as_uint(f);
  if ((u << 1) == 0u) return 0x80000000u;
  return (u & 0x80000000u) ? ~u : (u | 0x80000000u);
}

__device__ __forceinline__ float cand_val(int mode, int b, unsigned i, int HW){
  if (mode == 0){
    unsigned d = i / (unsigned)HW;
    return g_vals[d][(unsigned)b*HW + (i - d*(unsigned)HW)];
  }
  return g_cand_resp[b][i];
}

// ---------------- blur (templated taps, 2D grid, unfused mul+add) ----------------
template<int N>
__global__ void k_blurv_t(const float* __restrict__ src, float* __restrict__ dst,
                          int H,int W, KW kw){
  int x = blockIdx.x*128 + threadIdx.x;
  int y = blockIdx.y, b = blockIdx.z;
  if (x >= W) return;
  const int P = N/2;
  const float* s = src + b*H*W;
  float acc = 0.f;
  if (y >= P && y + P < H){
    #pragma unroll
    for (int i=0;i<N;i++)
      acc = __fadd_rn(acc, __fmul_rn(kw.w[i], s[(y+i-P)*W + x]));
  } else {
    #pragma unroll
    for (int i=0;i<N;i++){
      int t = y+i-P;
      t = (t<0) ? -t : ((t>=H) ? (2*H-2-t) : t);
      acc = __fadd_rn(acc, __fmul_rn(kw.w[i], s[t*W + x]));
    }
  }
  dst[b*H*W + y*W + x] = acc;
}

template<int N>
__global__ void k_blurh_t(const float* __restrict__ src, float* __restrict__ dst,
                          int H,int W, KW kw){
  int x = blockIdx.x*128 + threadIdx.x;
  int y = blockIdx.y, b = blockIdx.z;
  if (x >= W) return;
  const int P = N/2;
  const float* s = src + b*H*W + y*W;
  float acc = 0.f;
  if (x >= P && x + P < W){
    #pragma unroll
    for (int i=0;i<N;i++)
      acc = __fadd_rn(acc, __fmul_rn(kw.w[i], s[x+i-P]));
  } else {
    #pragma unroll
    for (int i=0;i<N;i++){
      int t = x+i-P;
      t = (t<0) ? -t : ((t>=W) ? (2*W-2-t) : t);
      acc = __fadd_rn(acc, __fmul_rn(kw.w[i], s[t]));
    }
  }
  dst[b*H*W + y*W + x] = acc;
}

__global__ void k_down(int S){
  int idx = blockIdx.x*blockDim.x + threadIdx.x;
  int HW = S*S, tot = 2*HW; if (idx >= tot) return;
  int b = idx/HW, rem = idx-b*HW;
  int y = rem/S, x = rem-(rem/S)*S;
  int S2 = 2*S, HW2 = 4*HW;
  g_lv[0][idx] = g_lv[3][b*HW2 + (2*y)*S2 + 2*x];
}

// ---------------- hessian: smem-tiled, kh outer / kw inner, UNFUSED ----------------
__global__ void k_hess2(int H,int W,float q0,float q1,float q2,float q3,float q4){
  int l = blockIdx.z % 5, b = blockIdx.z / 5;
  int x0 = blockIdx.x*BX, y0 = blockIdx.y*BY;
  __shared__ float t[BY+4][BX+4];
  const float* s = &g_lv[l][b*H*W];
  for (int j = threadIdx.y; j < BY+4; j += BY){
    int yy = y0 + j - 2; yy = yy<0?0:(yy>H-1?H-1:yy);
    for (int i = threadIdx.x; i < BX+4; i += BX){
      int xx = x0 + i - 2; xx = xx<0?0:(xx>W-1?W-1:xx);
      t[j][i] = s[yy*W+xx];
    }
  }
  __syncthreads();
  int x = x0 + threadIdx.x, y = y0 + threadIdx.y;
  if (x >= W || y >= H) return;
  float dxx=0.f,dxy=0.f,dyy=0.f;
  #pragma unroll
  for (int i=0;i<5;i++){
    #pragma unroll
    for (int j=0;j<5;j++){
      float pv = t[threadIdx.y+i][threadIdx.x+j];
      dxx = __fadd_rn(dxx, __fmul_rn(cGXX[i*5+j], pv));
      dxy = __fadd_rn(dxy, __fmul_rn(cGXY[i*5+j], pv));
      dyy = __fadd_rn(dyy, __fmul_rn(cGYY[i*5+j], pv));
    }
  }
  float s4 = (l==0)?q0:(l==1)?q1:(l==2)?q2:(l==3)?q3:q4;
  float det = __fsub_rn(__fmul_rn(dxx,dyy), __fmul_rn(dxy,dxy));
  g_resp[l][(size_t)b*H*W + y*W + x] = __fmul_rn(det, s4);
}

// ---------------- emap: tiled 3 planes, -FLT_MAX pad (max exact) ----------------
__global__ void k_emap2(int H,int W){
  int l = blockIdx.z % 5, b = blockIdx.z / 5;
  int x0 = blockIdx.x*BX, y0 = blockIdx.y*BY;
  int HW = H*W;
  __shared__ float t[3][BY+2][BX+2];
  for (int p=0;p<3;p++){
    int dd = l-1+p;
    bool pv = (dd>=0 && dd<=4);
    const float* rp = pv ? &g_resp[dd][b*HW] : 0;
    for (int j = threadIdx.y; j < BY+2; j += BY){
      int gy = y0 - 1 + j;
      for (int i = threadIdx.x; i < BX+2; i += BX){
        int gx = x0 - 1 + i;
        bool ok = pv && gy>=0 && gy<H && gx>=0 && gx<W;
        t[p][j][i] = ok ? rp[gy*W+gx] : -3.402823466e38f;
      }
    }
  }
  __syncthreads();
  int x = x0 + threadIdx.x, y = y0 + threadIdx.y;
  if (x >= W || y >= H) return;
  float m = -3.402823466e38f;
  #pragma unroll
  for (int p=0;p<3;p++)
    #pragma unroll
    for (int j=0;j<3;j++)
      #pragma unroll
      for (int i=0;i<3;i++)
        m = fmaxf(m, t[p][threadIdx.y+j][threadIdx.x+i]);
  float c = t[1][threadIdx.y+1][threadIdx.x+1];
  g_e[l][b*HW + y*W + x] = xla_expf(__fsub_rn(c, m));
}

// ---------------- vals: tiled 6 planes, +0 pad (exact no-op), fused round-0 hist ----
__global__ void k_vals2(int H,int W){
  int l = blockIdx.z % 5, b = blockIdx.z / 5;
  int x0 = blockIdx.x*BX, y0 = blockIdx.y*BY;
  int HW = H*W;
  __shared__ float te[3][BY+2][BX+2];
  __shared__ float tr[3][BY+2][BX+2];
  __shared__ unsigned sh[256];
  int tid = threadIdx.y*BX + threadIdx.x;
  sh[tid] = 0u;
  for (int p=0;p<3;p++){
    int dd = l-1+p;
    bool pv = (dd>=0 && dd<=4);
    const float* ep = pv ? &g_e[dd][b*HW] : 0;
    const float* rp = pv ? &g_resp[dd][b*HW] : 0;
    for (int j = threadIdx.y; j < BY+2; j += BY){
      int gy = y0 - 1 + j;
      for (int i = threadIdx.x; i < BX+2; i += BX){
        int gx = x0 - 1 + i;
        bool ok = pv && gy>=0 && gy<H && gx>=0 && gx<W;
        te[p][j][i] = ok ? ep[gy*W+gx] : 0.f;
        tr[p][j][i] = ok ? rp[gy*W+gx] : 0.f;
      }
    }
  }
  __syncthreads();
  int x = x0 + threadIdx.x, y = y0 + threadIdx.y;
  if (x < W && y < H){
    // exact original order (d,h,w); padded zeros are exact no-ops
    float den=0.f, num=0.f;
    #pragma unroll
    for (int p=0;p<3;p++)
      #pragma unroll
      for (int j=0;j<3;j++)
        #pragma unroll
        for (int i=0;i<3;i++){
          float ev = te[p][threadIdx.y+j][threadIdx.x+i];
          den = __fadd_rn(den, ev);
          num = __fadd_rn(num, __fmul_rn(ev, tr[p][threadIdx.y+j][threadIdx.x+i]));
        }
    float v = __fdiv_rn(num, __fadd_rn(den, EPSF));
    g_vals[l][b*HW + y*W + x] = v;
    atomicAdd(&sh[fkey(v)>>24], 1u);     // fused radix round-0 histogram
  }
  __syncthreads();
  if (sh[tid]) atomicAdd(&g_bins[b][tid], sh[tid]);
}

// ---------------- top-k machinery ----------------
__global__ void k_tkinit(){
  int t = threadIdx.x;
  if (t < 2){ g_prefix[t]=0u; g_kremain[t]=NFEAT; g_candcnt[t]=0u; g_cnt1[t]=0u; }
  for (int i=t;i<512;i+=blockDim.x) ((unsigned*)g_bins)[i]=0u;
}

__global__ void k_scan(){
  int b = threadIdx.x; if (b >= 2) return;
  unsigned k = g_kremain[b];
  unsigned cum = 0; int dsel = 0;
  for (int d=255; d>=0; d--){
    unsigned c = g_bins[b][d];
    if (cum + c >= k){ dsel = d; break; }
    cum += c;
  }
  g_prefix[b] = (g_prefix[b]<<8) | (unsigned)dsel;
  g_kremain[b] = k - cum;
  g_thresh[b] = g_prefix[b];
  for (int t=0;t<256;t++) g_bins[b][t]=0u;
}

// compact all elements whose top byte >= dsel0 into g_cand1 (1 full scan)
__global__ void k_compact1(int N,int HW){
  int b = blockIdx.y;
  unsigned pref = g_prefix[b];   // after round-0 scan: single byte
  for (int i=blockIdx.x*blockDim.x+threadIdx.x; i<N; i+=gridDim.x*blockDim.x){
    unsigned key = fkey(cand_val(0,b,(unsigned)i,HW));
    if ((key>>24) >= pref){
      unsigned p = atomicAdd(&g_cnt1[b], 1u);
      if (p < C1CAP) g_cand1[b][p] = (unsigned)i;
    }
  }
}

// radix rounds 1..3 over the compacted list
__global__ void k_hist_l(int HW,int r){
  __shared__ unsigned sh[256];
  int b = blockIdx.y;
  for (int i=threadIdx.x;i<256;i+=blockDim.x) sh[i]=0u;
  __syncthreads();
  unsigned M = g_cnt1[b]; if (M > C1CAP) M = C1CAP;
  unsigned pref = g_prefix[b];
  int shift = 24 - 8*r;
  for (unsigned i=blockIdx.x*blockDim.x+threadIdx.x; i<M; i+=gridDim.x*blockDim.x){
    unsigned key = fkey(cand_val(0,b,g_cand1[b][i],HW));
    if ((key >> (8*(4-r))) == pref) atomicAdd(&sh[(key>>shift)&0xFFu], 1u);
  }
  __syncthreads();
  for (int i=threadIdx.x;i<256;i+=blockDim.x)
    if (sh[i]) atomicAdd(&g_bins[b][i], sh[i]);
}

__global__ void k_compact2(int HW){
  int b = blockIdx.y;
  unsigned M = g_cnt1[b]; if (M > C1CAP) M = C1CAP;
  unsigned T = g_thresh[b];
  for (unsigned i=blockIdx.x*blockDim.x+threadIdx.x; i<M; i+=gridDim.x*blockDim.x){
    unsigned idx = g_cand1[b][i];
    unsigned key = fkey(cand_val(0,b,idx,HW));
    if (key >= T){
      unsigned p = atomicAdd(&g_candcnt[b], 1u);
      if (p < CANDCAP) g_candlist[b][p] = idx;
    }
  }
}

// final-selection path (13280 candidates): full scans are tiny
__global__ void k_hist(int mode,int N,int HW,int r){
  __shared__ unsigned sh[256];
  int b = blockIdx.y;
  for (int i=threadIdx.x;i<256;i+=blockDim.x) sh[i]=0u;
  __syncthreads();
  unsigned pref = g_prefix[b];
  int shift = 24 - 8*r;
  for (int i=blockIdx.x*blockDim.x+threadIdx.x; i<N; i+=gridDim.x*blockDim.x){
    unsigned key = fkey(cand_val(mode,b,(unsigned)i,HW));
    bool ok = (r==0) || ((key >> (8*(4-r))) == pref);
    if (ok) atomicAdd(&sh[(key>>shift)&0xFFu], 1u);
  }
  __syncthreads();
  for (int i=threadIdx.x;i<256;i+=blockDim.x)
    if (sh[i]) atomicAdd(&g_bins[b][i], sh[i]);
}

__global__ void k_compact(int mode,int N,int HW){
  int b = blockIdx.y;
  unsigned T = g_thresh[b];
  for (int i=blockIdx.x*blockDim.x+threadIdx.x; i<N; i+=gridDim.x*blockDim.x){
    unsigned key = fkey(cand_val(mode,b,(unsigned)i,HW));
    if (key >= T){
      unsigned p = atomicAdd(&g_candcnt[b], 1u);
      if (p < CANDCAP) g_candlist[b][p] = (unsigned)i;
    }
  }
}

__global__ void k_sortsel(int mode,int HW,int outmode){
  __shared__ unsigned long long s[SORTN];
  int b = blockIdx.x;
  unsigned M = g_candcnt[b]; if (M > CANDCAP) M = CANDCAP;
  for (int t=threadIdx.x; t<SORTN; t+=blockDim.x){
    unsigned long long kv = 0ULL;
    if (t < (int)M){
      unsigned i = g_candlist[b][t];
      kv = ((unsigned long long)fkey(cand_val(mode,b,i,HW)) << 32) | (unsigned)(~i);
    }
    s[t] = kv;
  }
  __syncthreads();
  for (int k=2; k<=SORTN; k<<=1){
    for (int j=k>>1; j>0; j>>=1){
      for (int i=threadIdx.x; i<SORTN; i+=blockDim.x){
        int p = i ^ j;
        if (p > i){
          unsigned long long a=s[i], c=s[p];
          bool up = ((i & k) == 0);
          if (up ? (a < c) : (a > c)){ s[i]=c; s[p]=a; }
        }
      }
      __syncthreads();
    }
  }
  for (int t=threadIdx.x; t<NFEAT; t+=blockDim.x){
    unsigned i = ~((unsigned)(s[t] & 0xFFFFFFFFULL));
    float v = cand_val(mode,b,i,HW);
    if (outmode==0){ g_selidx[b][t]=i; g_selval[b][t]=v; }
    else           { g_finidx[b][t]=i; g_finval[b][t]=v; }
  }
}

__global__ void k_laf(int H,int W,int count,int use_sel,int base){
  int j = blockIdx.x*blockDim.x + threadIdx.x;
  int b = blockIdx.y;
  if (j >= count) return;
  int HW = H*W;
  unsigned idx; float v;
  if (use_sel){ idx = g_selidx[b][j]; v = g_selval[b][j]; }
  else {
    idx = (unsigned)j;
    unsigned d0 = idx/(unsigned)HW;
    v = g_vals[d0][(unsigned)b*HW + (idx - d0*(unsigned)HW)];
  }
  int d = idx/HW, rem = idx-d*HW;
  int y = rem/W, x = rem-(rem/W)*W;
  float den=0.f, sd=0.f, sx=0.f, sy=0.f;
  for (int dd=d-1; dd<=d+1; dd++){
    if (dd<0 || dd>4) continue;
    const float* e = &g_e[dd][b*HW];
    for (int yy=y-1; yy<=y+1; yy++){
      if ((unsigned)yy >= (unsigned)H) continue;
      for (int xx=x-1; xx<=x+1; xx++){
        if ((unsigned)xx >= (unsigned)W) continue;
        float ev = e[yy*W+xx];
        den = __fadd_rn(den, ev);
        if (dd != d) sd = __fadd_rn(sd, __fmul_rn(ev, (float)(dd-d)));
        if (xx != x) sx = __fadd_rn(sx, __fmul_rn(ev, (float)(xx-x)));
        if (yy != y) sy = __fadd_rn(sy, __fmul_rn(ev, (float)(yy-y)));
      }
    }
  }
  float dE = __fadd_rn(den, EPSF);
  float cd = __fadd_rn(__fdiv_rn(sd,dE), (float)d);
  float cx = __fadd_rn(__fdiv_rn(sx,dE), (float)x);
  float cy = __fadd_rn(__fdiv_rn(sy,dE), (float)y);
  float scale = __fmul_rn(1.6f, (float)exp2((double)__fdiv_rn(cd, 3.0f)));
  float s6 = __fmul_rn(6.0f, scale);
  float g = ((__fsub_rn(cx,s6) > 0.f) && (__fadd_rn(cx,s6) < (float)(W-1)) &&
             (__fsub_rn(cy,s6) > 0.f) && (__fadd_rn(cy,s6) < (float)(H-1))) ? 1.f : 0.f;
  float mn = (float)(H < W ? H : W);
  int o = base + j;
  g_cand_resp[b][o] = __fmul_rn(v, g);
  float* Lf = g_cand_laf[b][o];
  Lf[0] = __fdiv_rn(s6,mn); Lf[1] = 0.f; Lf[2] = __fdiv_rn(cx,(float)W);
  Lf[3] = 0.f;              Lf[4] = __fdiv_rn(s6,mn); Lf[5] = __fdiv_rn(cy,(float)H);
}

__global__ void k_out(float* __restrict__ out){
  int t = blockIdx.x*blockDim.x + threadIdx.x;
  if (t >= 2*NFEAT) return;
  int b = t/NFEAT, j = t-b*NFEAT;
  unsigned i = g_finidx[b][j];
  const float* L = g_cand_laf[b][i];
  float* o = out + (b*NFEAT + j)*6;
  #pragma unroll
  for (int e=0;e<6;e++) o[e] = __fmul_rn(L[e], 1024.0f);
  out[2*NFEAT*6 + b*NFEAT + j] = g_finval[b][j];
}

// ---------------- host ----------------
static void launch_blurv(const float* src, float* dst, int S, const KW& kw, int n){
  dim3 g((S+127)/128, S, 2);
  switch(n){
    case 9:  k_blurv_t<9 ><<<g,128>>>(src,dst,S,S,kw); break;
    case 11: k_blurv_t<11><<<g,128>>>(src,dst,S,S,kw); break;
    case 13: k_blurv_t<13><<<g,128>>>(src,dst,S,S,kw); break;
    case 15: k_blurv_t<15><<<g,128>>>(src,dst,S,S,kw); break;
    case 17: k_blurv_t<17><<<g,128>>>(src,dst,S,S,kw); break;
    case 19: k_blurv_t<19><<<g,128>>>(src,dst,S,S,kw); break;
    case 21: k_blurv_t<21><<<g,128>>>(src,dst,S,S,kw); break;
    default: k_blurv_t<23><<<g,128>>>(src,dst,S,S,kw); break;
  }
}
static void launch_blurh(const float* src, float* dst, int S, const KW& kw, int n){
  dim3 g((S+127)/128, S, 2);
  switch(n){
    case 9:  k_blurh_t<9 ><<<g,128>>>(src,dst,S,S,kw); break;
    case 11: k_blurh_t<11><<<g,128>>>(src,dst,S,S,kw); break;
    case 13: k_blurh_t<13><<<g,128>>>(src,dst,S,S,kw); break;
    case 15: k_blurh_t<15><<<g,128>>>(src,dst,S,S,kw); break;
    case 17: k_blurh_t<17><<<g,128>>>(src,dst,S,S,kw); break;
    case 19: k_blurh_t<19><<<g,128>>>(src,dst,S,S,kw); break;
    case 21: k_blurh_t<21><<<g,128>>>(src,dst,S,S,kw); break;
    default: k_blurh_t<23><<<g,128>>>(src,dst,S,S,kw); break;
  }
}

extern "C" void kernel_launch(void* const* d_in, const int* in_sizes, int n_in,
                              void* d_out, int out_size){
  (void)in_sizes; (void)n_in; (void)out_size;
  const float* img = (const float*)d_in[0];
  float* out = (float*)d_out;

  float *p_lv = 0, *p_tmp = 0;
  cudaGetSymbolAddress((void**)&p_lv, g_lv);
  cudaGetSymbolAddress((void**)&p_tmp, g_tmp);

  double step = pow(2.0, 1.0/3.0);
  double q = sqrt(step*step - 1.0);
  double sgm[5]; int ksz[5];
  sgm[0] = sqrt(1.6*1.6 - 0.25);
  { double cs = 1.6; for (int i=1;i<5;i++){ sgm[i] = cs * q; cs *= step; } }
  for (int i=0;i<5;i++){ int k=(int)(8.0*sgm[i]+1.0); if(!(k&1))k++; ksz[i]=k; }
  float s4[5];
  { double cs = 1.6;
    for (int l=0;l<5;l++){ float sgf=(float)cs; s4[l]=powf(sgf,4.0f); cs*=step; } }

  // host weight pipeline: identical f32 op sequence to former k_initg
  KW kws[5];
  for (int t=0;t<5;t++){
    int n = ksz[t], h = n/2;
    volatile float den2 = (float)(2.0*sgm[t]*sgm[t]);
    float w[32];
    for (int i=0;i<n;i++){
      volatile float x = (float)(i - h);
      volatile float arg = -(x*x)/den2;
      w[i] = (float)exp((double)arg);           // CR exp, f32 round
    }
    volatile float r[8];
    for (int j=0;j<8;j++) r[j] = w[j];
    int i = 8;
    for (; i + 8 <= n; i += 8)
      for (int j=0;j<8;j++) r[j] = r[j] + w[i+j];
    volatile float s01 = r[0]+r[1], s23 = r[2]+r[3], s45 = r[4]+r[5], s67 = r[6]+r[7];
    volatile float s0123 = s01+s23, s4567 = s45+s67;
    volatile float sum = s0123 + s4567;
    for (; i < n; i++) sum = sum + w[i];
    for (int k2=0;k2<24;k2++) kws[t].w[k2] = 0.f;
    for (int k2=0;k2<n;k2++) kws[t].w[k2] = w[k2]/sum;
  }

  static const int SS[7] = {1024,512,256,128,64,32,16};
  int base = 0;
  for (int o=0;o<7;o++){
    int S = SS[o], HW = S*S, tot = 2*HW;
    if (o == 0){
      launch_blurv(img, p_tmp, S, kws[0], ksz[0]);
      launch_blurh(p_tmp, p_lv, S, kws[0], ksz[0]);
    } else {
      int thr = 256, blk = (tot+thr-1)/thr;
      k_down<<<blk,thr>>>(S);
    }
    for (int i=1;i<5;i++){
      launch_blurv(p_lv+(i-1)*LVS, p_tmp, S, kws[i], ksz[i]);
      launch_blurh(p_tmp, p_lv+i*LVS, S, kws[i], ksz[i]);
    }
    dim3 tg((S+BX-1)/BX, (S+BY-1)/BY, 10);
    dim3 tb(BX, BY);
    k_hess2<<<tg,tb>>>(S,S,s4[0],s4[1],s4[2],s4[3],s4[4]);
    k_emap2<<<tg,tb>>>(S,S);
    k_tkinit<<<1,256>>>();           // zero bins BEFORE fused hist in vals
    k_vals2<<<tg,tb>>>(S,S);

    int N = 5*HW;
    if (N > NFEAT){
      k_scan<<<1,2>>>();                                  // round 0 (hist fused)
      int hb = (N+255)/256; if (hb > 2048) hb = 2048;
      k_compact1<<<dim3(hb,2),256>>>(N,HW);               // 1 full scan
      for (int r=1;r<4;r++){
        k_hist_l<<<dim3(16,2),256>>>(HW,r);               // tiny
        k_scan<<<1,2>>>();
      }
      k_compact2<<<dim3(16,2),256>>>(HW);                 // tiny
      k_sortsel<<<2,512>>>(0,HW,0);
      k_laf<<<dim3((NFEAT+127)/128,2),128>>>(S,S,NFEAT,1,base);
      base += NFEAT;
    } else {
      k_laf<<<dim3((N+127)/128,2),128>>>(S,S,N,0,base);
      base += N;
    }
  }

  // final selection over all candidates (base == 13280)
  int N = base;
  k_tkinit<<<1,256>>>();
  int hb = (N+255)/256;
  for (int r=0;r<4;r++){
    k_hist<<<dim3(hb,2),256>>>(1,N,0,r);
    k_scan<<<1,2>>>();
  }
  k_compact<<<dim3(hb,2),256>>>(1,N,0);
  k_sortsel<<<2,512>>>(1,0,1);
  k_out<<<(2*NFEAT+255)/256,256>>>(out);
}

// round 13
// speedup vs baseline: 1.1721x; 1.0554x over previous
#include <cuda_runtime.h>
#include <math.h>

#define NFEAT   2000
#define TOTCAND 13280
#define MAXHW   (1024*1024)
#define LVS     (2*MAXHW)
#define EPSF    1e-8f
#define CANDCAP 4096
#define SORTN   4096
#define C1CAP   262144
#define BX 32
#define BY 8

// ---------------- static device scratch ----------------
__device__ float g_lv[5][LVS];
__device__ float g_tmp[LVS];
__device__ float g_resp[5][LVS];
__device__ float g_e[5][LVS];
__device__ float g_vals[5][LVS];

__device__ unsigned g_bins[2][256];
__device__ unsigned g_candcnt[2];
__device__ unsigned g_cnt1[2];
__device__ unsigned g_cand1[2][C1CAP];
__device__ unsigned g_candlist[2][CANDCAP];
__device__ unsigned g_selidx[2][NFEAT];
__device__ float    g_selval[2][NFEAT];
__device__ float    g_cand_resp[2][TOTCAND];
__device__ float    g_cand_laf[2][TOTCAND][6];
__device__ unsigned g_finidx[2][NFEAT];
__device__ float    g_finval[2][NFEAT];

struct KW { float w[24]; };   // blur weights passed by value (const bank)

// Hessian kernels (reference _K2 / abs-sum: /64, /36, /64; f32-exact constants)
__constant__ float cGXX[25] = {
 -1.f/64,0.f,2.f/64,0.f,-1.f/64, -4.f/64,0.f,8.f/64,0.f,-4.f/64,
 -6.f/64,0.f,12.f/64,0.f,-6.f/64, -4.f/64,0.f,8.f/64,0.f,-4.f/64,
 -1.f/64,0.f,2.f/64,0.f,-1.f/64 };
__constant__ float cGXY[25] = {
 (float)(-1.0/36),(float)(-2.0/36),0.f,(float)(2.0/36),(float)(1.0/36),
 (float)(-2.0/36),(float)(-4.0/36),0.f,(float)(4.0/36),(float)(2.0/36),
 0.f,0.f,0.f,0.f,0.f,
 (float)(2.0/36),(float)(4.0/36),0.f,(float)(-4.0/36),(float)(-2.0/36),
 (float)(1.0/36),(float)(2.0/36),0.f,(float)(-2.0/36),(float)(-1.0/36) };
__constant__ float cGYY[25] = {     // _GXX.T
 -1.f/64,-4.f/64,-6.f/64,-4.f/64,-1.f/64, 0.f,0.f,0.f,0.f,0.f,
 2.f/64,8.f/64,12.f/64,8.f/64,2.f/64, 0.f,0.f,0.f,0.f,0.f,
 -1.f/64,-4.f/64,-6.f/64,-4.f/64,-1.f/64 };

// XLA-CPU inline exp (Cephes), every mul/add UNFUSED — bit-exact
__device__ __forceinline__ float xla_expf(float input){
  float x = fminf(input, 88.3762626647950f);
  x = fmaxf(x, -88.3762626647949f);
  float fx = floorf(__fadd_rn(__fmul_rn(x, 1.44269504088896341f), 0.5f));
  float tmp = __fmul_rn(fx, 0.693359375f);
  float z   = __fmul_rn(fx, -2.12194440e-4f);
  x = __fsub_rn(x, tmp);
  x = __fsub_rn(x, z);
  float z2 = __fmul_rn(x, x);
  float y = 1.9875691500E-4f;
  y = __fadd_rn(__fmul_rn(y, x), 1.3981999507E-3f);
  y = __fadd_rn(__fmul_rn(y, x), 8.3334519073E-3f);
  y = __fadd_rn(__fmul_rn(y, x), 4.1665795894E-2f);
  y = __fadd_rn(__fmul_rn(y, x), 1.6666665459E-1f);
  y = __fadd_rn(__fmul_rn(y, x), 5.0000001201E-1f);
  y = __fadd_rn(__fmul_rn(y, z2), x);
  y = __fadd_rn(y, 1.0f);
  int n = (int)fx;
  float p2n = __uint_as_float((unsigned)(n + 127) << 23);
  return __fmul_rn(y, p2n);
}

__device__ __forceinline__ unsigned fkey(float f){
  unsigned u = __float_as_uint(f);
  if ((u << 1) == 0u) return 0x80000000u;
  return (u & 0x80000000u) ? ~u : (u | 0x80000000u);
}

__device__ __forceinline__ float cand_val(int mode, int b, unsigned i, int HW){
  if (mode == 0){
    unsigned d = i / (unsigned)HW;
    return g_vals[d][(unsigned)b*HW + (i - d*(unsigned)HW)];
  }
  return g_cand_resp[b][i];
}

// ---------------- blur: 2 rows per thread (ILP 2), unfused mul+add ----------------
template<int N>
__global__ void k_blurv_t(const float* __restrict__ src, float* __restrict__ dst,
                          int H,int W, KW kw){
  int x = blockIdx.x*128 + threadIdx.x;
  int y0 = blockIdx.y*2, b = blockIdx.z;
  if (x >= W) return;
  const int P = N/2;
  const float* s = src + b*H*W;
  float acc0 = 0.f, acc1 = 0.f;
  if (y0 >= P && y0 + 1 + P < H){
    float v[N+1];
    #pragma unroll
    for (int i=0;i<=N;i++) v[i] = s[(y0-P+i)*W + x];
    #pragma unroll
    for (int i=0;i<N;i++){
      acc0 = __fadd_rn(acc0, __fmul_rn(kw.w[i], v[i]));
      acc1 = __fadd_rn(acc1, __fmul_rn(kw.w[i], v[i+1]));
    }
  } else {
    #pragma unroll
    for (int i=0;i<N;i++){
      int t0 = y0+i-P;
      t0 = (t0<0) ? -t0 : ((t0>=H) ? (2*H-2-t0) : t0);
      int t1 = y0+1+i-P;
      t1 = (t1<0) ? -t1 : ((t1>=H) ? (2*H-2-t1) : t1);
      acc0 = __fadd_rn(acc0, __fmul_rn(kw.w[i], s[t0*W + x]));
      acc1 = __fadd_rn(acc1, __fmul_rn(kw.w[i], s[t1*W + x]));
    }
  }
  dst[b*H*W + y0*W + x] = acc0;
  dst[b*H*W + (y0+1)*W + x] = acc1;
}

template<int N>
__global__ void k_blurh_t(const float* __restrict__ src, float* __restrict__ dst,
                          int H,int W, KW kw){
  int x = blockIdx.x*128 + threadIdx.x;
  int y0 = blockIdx.y*2, b = blockIdx.z;
  if (x >= W) return;
  const int P = N/2;
  const float* s0 = src + b*H*W + y0*W;
  const float* s1 = s0 + W;
  float acc0 = 0.f, acc1 = 0.f;
  if (x >= P && x + P < W){
    #pragma unroll
    for (int i=0;i<N;i++){
      acc0 = __fadd_rn(acc0, __fmul_rn(kw.w[i], s0[x+i-P]));
      acc1 = __fadd_rn(acc1, __fmul_rn(kw.w[i], s1[x+i-P]));
    }
  } else {
    #pragma unroll
    for (int i=0;i<N;i++){
      int t = x+i-P;
      t = (t<0) ? -t : ((t>=W) ? (2*W-2-t) : t);
      acc0 = __fadd_rn(acc0, __fmul_rn(kw.w[i], s0[t]));
      acc1 = __fadd_rn(acc1, __fmul_rn(kw.w[i], s1[t]));
    }
  }
  dst[b*H*W + y0*W + x] = acc0;
  dst[b*H*W + (y0+1)*W + x] = acc1;
}

__global__ void k_down(int S){
  int idx = blockIdx.x*blockDim.x + threadIdx.x;
  int HW = S*S, tot = 2*HW; if (idx >= tot) return;
  int b = idx/HW, rem = idx-b*HW;
  int y = rem/S, x = rem-(rem/S)*S;
  int S2 = 2*S, HW2 = 4*HW;
  g_lv[0][idx] = g_lv[3][b*HW2 + (2*y)*S2 + 2*x];
}

// ---------------- hessian: smem-tiled, kh outer / kw inner, UNFUSED ----------------
__global__ void k_hess2(int H,int W,float q0,float q1,float q2,float q3,float q4){
  int l = blockIdx.z % 5, b = blockIdx.z / 5;
  int x0 = blockIdx.x*BX, y0 = blockIdx.y*BY;
  __shared__ float t[BY+4][BX+4];
  const float* s = &g_lv[l][b*H*W];
  for (int j = threadIdx.y; j < BY+4; j += BY){
    int yy = y0 + j - 2; yy = yy<0?0:(yy>H-1?H-1:yy);
    for (int i = threadIdx.x; i < BX+4; i += BX){
      int xx = x0 + i - 2; xx = xx<0?0:(xx>W-1?W-1:xx);
      t[j][i] = s[yy*W+xx];
    }
  }
  __syncthreads();
  int x = x0 + threadIdx.x, y = y0 + threadIdx.y;
  if (x >= W || y >= H) return;
  float dxx=0.f,dxy=0.f,dyy=0.f;
  #pragma unroll
  for (int i=0;i<5;i++){
    #pragma unroll
    for (int j=0;j<5;j++){
      float pv = t[threadIdx.y+i][threadIdx.x+j];
      dxx = __fadd_rn(dxx, __fmul_rn(cGXX[i*5+j], pv));
      dxy = __fadd_rn(dxy, __fmul_rn(cGXY[i*5+j], pv));
      dyy = __fadd_rn(dyy, __fmul_rn(cGYY[i*5+j], pv));
    }
  }
  float s4 = (l==0)?q0:(l==1)?q1:(l==2)?q2:(l==3)?q3:q4;
  float det = __fsub_rn(__fmul_rn(dxx,dyy), __fmul_rn(dxy,dxy));
  g_resp[l][(size_t)b*H*W + y*W + x] = __fmul_rn(det, s4);
}

// ---------------- emap: tiled 3 planes, -FLT_MAX pad (max exact) ----------------
__global__ void k_emap2(int H,int W){
  int l = blockIdx.z % 5, b = blockIdx.z / 5;
  int x0 = blockIdx.x*BX, y0 = blockIdx.y*BY;
  int HW = H*W;
  __shared__ float t[3][BY+2][BX+2];
  for (int p=0;p<3;p++){
    int dd = l-1+p;
    bool pv = (dd>=0 && dd<=4);
    const float* rp = pv ? &g_resp[dd][b*HW] : 0;
    for (int j = threadIdx.y; j < BY+2; j += BY){
      int gy = y0 - 1 + j;
      for (int i = threadIdx.x; i < BX+2; i += BX){
        int gx = x0 - 1 + i;
        bool ok = pv && gy>=0 && gy<H && gx>=0 && gx<W;
        t[p][j][i] = ok ? rp[gy*W+gx] : -3.402823466e38f;
      }
    }
  }
  __syncthreads();
  int x = x0 + threadIdx.x, y = y0 + threadIdx.y;
  if (x >= W || y >= H) return;
  float m = -3.402823466e38f;
  #pragma unroll
  for (int p=0;p<3;p++)
    #pragma unroll
    for (int j=0;j<3;j++)
      #pragma unroll
      for (int i=0;i<3;i++)
        m = fmaxf(m, t[p][threadIdx.y+j][threadIdx.x+i]);
  float c = t[1][threadIdx.y+1][threadIdx.x+1];
  g_e[l][b*HW + y*W + x] = xla_expf(__fsub_rn(c, m));
}

// ---------------- vals: tiled, +0 pad (exact no-op), fused round-0 hist ----------
__global__ void k_vals2(int H,int W){
  int l = blockIdx.z % 5, b = blockIdx.z / 5;
  int x0 = blockIdx.x*BX, y0 = blockIdx.y*BY;
  int HW = H*W;
  __shared__ float te[3][BY+2][BX+2];
  __shared__ float tr[3][BY+2][BX+2];
  __shared__ unsigned sh[256];
  int tid = threadIdx.y*BX + threadIdx.x;
  sh[tid] = 0u;
  for (int p=0;p<3;p++){
    int dd = l-1+p;
    bool pv = (dd>=0 && dd<=4);
    const float* ep = pv ? &g_e[dd][b*HW] : 0;
    const float* rp = pv ? &g_resp[dd][b*HW] : 0;
    for (int j = threadIdx.y; j < BY+2; j += BY){
      int gy = y0 - 1 + j;
      for (int i = threadIdx.x; i < BX+2; i += BX){
        int gx = x0 - 1 + i;
        bool ok = pv && gy>=0 && gy<H && gx>=0 && gx<W;
        te[p][j][i] = ok ? ep[gy*W+gx] : 0.f;
        tr[p][j][i] = ok ? rp[gy*W+gx] : 0.f;
      }
    }
  }
  __syncthreads();
  int x = x0 + threadIdx.x, y = y0 + threadIdx.y;
  if (x < W && y < H){
    float den=0.f, num=0.f;
    #pragma unroll
    for (int p=0;p<3;p++)
      #pragma unroll
      for (int j=0;j<3;j++)
        #pragma unroll
        for (int i=0;i<3;i++){
          float ev = te[p][threadIdx.y+j][threadIdx.x+i];
          den = __fadd_rn(den, ev);
          num = __fadd_rn(num, __fmul_rn(ev, tr[p][threadIdx.y+j][threadIdx.x+i]));
        }
    float v = __fdiv_rn(num, __fadd_rn(den, EPSF));
    g_vals[l][b*HW + y*W + x] = v;
    atomicAdd(&sh[fkey(v)>>24], 1u);
  }
  __syncthreads();
  if (sh[tid]) atomicAdd(&g_bins[b][tid], sh[tid]);
}

// ---------------- top-k machinery ----------------
__global__ void k_tkinit(){
  int t = threadIdx.x;
  if (t < 2){ g_candcnt[t]=0u; g_cnt1[t]=0u; }
  for (int i=t;i<512;i+=blockDim.x) ((unsigned*)g_bins)[i]=0u;
}

// compact all elements whose top byte >= dsel0 (self-computed round-0 scan)
__global__ void k_compact1(int N,int HW){
  int b = blockIdx.y;
  __shared__ unsigned sdsel;
  if (threadIdx.x == 0){
    unsigned k = NFEAT, cum = 0; unsigned dsel = 0;
    for (int d=255; d>=0; d--){
      unsigned c = g_bins[b][d];
      if (cum + c >= k){ dsel = (unsigned)d; break; }
      cum += c;
    }
    sdsel = dsel;
  }
  __syncthreads();
  unsigned dsel = sdsel;
  for (int i=blockIdx.x*blockDim.x+threadIdx.x; i<N; i+=gridDim.x*blockDim.x){
    unsigned key = fkey(cand_val(0,b,(unsigned)i,HW));
    if ((key>>24) >= dsel){
      unsigned p = atomicAdd(&g_cnt1[b], 1u);
      if (p < C1CAP) g_cand1[b][p] = (unsigned)i;
    }
  }
}

// fused radix rounds 1..3 + final compact, one block per batch
__global__ void k_tail(int HW){
  int b = blockIdx.x;
  __shared__ unsigned bins[256];
  __shared__ unsigned spref, skrem, scnt;
  int tid = threadIdx.x;                 // 1024 threads
  unsigned M = g_cnt1[b]; if (M > C1CAP) M = C1CAP;
  if (tid == 0){
    unsigned k = NFEAT, cum = 0; unsigned dsel = 0;
    for (int d=255; d>=0; d--){
      unsigned c = g_bins[b][d];
      if (cum + c >= k){ dsel = (unsigned)d; break; }
      cum += c;
    }
    spref = dsel; skrem = k - cum;
  }
  __syncthreads();
  for (int r=1;r<4;r++){
    if (tid < 256) bins[tid] = 0u;
    __syncthreads();
    unsigned pref = spref;
    int shift = 24 - 8*r;
    for (unsigned i=tid; i<M; i+=1024){
      unsigned key = fkey(cand_val(0,b,g_cand1[b][i],HW));
      if ((key >> (8*(4-r))) == pref) atomicAdd(&bins[(key>>shift)&0xFFu], 1u);
    }
    __syncthreads();
    if (tid == 0){
      unsigned k = skrem, cum = 0; unsigned dsel = 0;
      for (int d=255; d>=0; d--){
        unsigned c = bins[d];
        if (cum + c >= k){ dsel = (unsigned)d; break; }
        cum += c;
      }
      spref = (spref<<8) | dsel; skrem = k - cum;
      if (r == 3) scnt = 0u;
    }
    __syncthreads();
  }
  unsigned T = spref;
  for (unsigned i=tid; i<M; i+=1024){
    unsigned idx = g_cand1[b][i];
    unsigned key = fkey(cand_val(0,b,idx,HW));
    if (key >= T){
      unsigned p = atomicAdd(&scnt, 1u);
      if (p < CANDCAP) g_candlist[b][p] = idx;
    }
  }
  __syncthreads();
  if (tid == 0) g_candcnt[b] = scnt;
}

// final selection over g_cand_resp (rounds 0..3 + compact), one block per batch
__global__ void k_tailf(int N){
  int b = blockIdx.x;
  __shared__ unsigned bins[256];
  __shared__ unsigned spref, skrem, scnt;
  int tid = threadIdx.x;                 // 1024
  if (tid == 0){ spref = 0u; skrem = NFEAT; }
  __syncthreads();
  for (int r=0;r<4;r++){
    if (tid < 256) bins[tid] = 0u;
    __syncthreads();
    unsigned pref = spref;
    int shift = 24 - 8*r;
    for (int i=tid; i<N; i+=1024){
      unsigned key = fkey(g_cand_resp[b][i]);
      bool ok = (r==0) || ((key >> (8*(4-r))) == pref);
      if (ok) atomicAdd(&bins[(key>>shift)&0xFFu], 1u);
    }
    __syncthreads();
    if (tid == 0){
      unsigned k = skrem, cum = 0; unsigned dsel = 0;
      for (int d=255; d>=0; d--){
        unsigned c = bins[d];
        if (cum + c >= k){ dsel = (unsigned)d; break; }
        cum += c;
      }
      spref = (spref<<8) | dsel; skrem = k - cum;
      if (r == 3) scnt = 0u;
    }
    __syncthreads();
  }
  unsigned T = spref;
  for (int i=tid; i<N; i+=1024){
    unsigned key = fkey(g_cand_resp[b][i]);
    if (key >= T){
      unsigned p = atomicAdd(&scnt, 1u);
      if (p < CANDCAP) g_candlist[b][p] = (unsigned)i;
    }
  }
  __syncthreads();
  if (tid == 0) g_candcnt[b] = scnt;
}

__global__ void k_sortsel(int mode,int HW,int outmode){
  __shared__ unsigned long long s[SORTN];
  int b = blockIdx.x;
  unsigned M = g_candcnt[b]; if (M > CANDCAP) M = CANDCAP;
  for (int t=threadIdx.x; t<SORTN; t+=blockDim.x){
    unsigned long long kv = 0ULL;
    if (t < (int)M){
      unsigned i = g_candlist[b][t];
      kv = ((unsigned long long)fkey(cand_val(mode,b,i,HW)) << 32) | (unsigned)(~i);
    }
    s[t] = kv;
  }
  __syncthreads();
  for (int k=2; k<=SORTN; k<<=1){
    for (int j=k>>1; j>0; j>>=1){
      for (int i=threadIdx.x; i<SORTN; i+=blockDim.x){
        int p = i ^ j;
        if (p > i){
          unsigned long long a=s[i], c=s[p];
          bool up = ((i & k) == 0);
          if (up ? (a < c) : (a > c)){ s[i]=c; s[p]=a; }
        }
      }
      __syncthreads();
    }
  }
  for (int t=threadIdx.x; t<NFEAT; t+=blockDim.x){
    unsigned i = ~((unsigned)(s[t] & 0xFFFFFFFFULL));
    float v = cand_val(mode,b,i,HW);
    if (outmode==0){ g_selidx[b][t]=i; g_selval[b][t]=v; }
    else           { g_finidx[b][t]=i; g_finval[b][t]=v; }
  }
}

__global__ void k_laf(int H,int W,int count,int use_sel,int base){
  int j = blockIdx.x*blockDim.x + threadIdx.x;
  int b = blockIdx.y;
  if (j >= count) return;
  int HW = H*W;
  unsigned idx; float v;
  if (use_sel){ idx = g_selidx[b][j]; v = g_selval[b][j]; }
  else {
    idx = (unsigned)j;
    unsigned d0 = idx/(unsigned)HW;
    v = g_vals[d0][(unsigned)b*HW + (idx - d0*(unsigned)HW)];
  }
  int d = idx/HW, rem = idx-d*HW;
  int y = rem/W, x = rem-(rem/W)*W;
  float den=0.f, sd=0.f, sx=0.f, sy=0.f;
  for (int dd=d-1; dd<=d+1; dd++){
    if (dd<0 || dd>4) continue;
    const float* e = &g_e[dd][b*HW];
    for (int yy=y-1; yy<=y+1; yy++){
      if ((unsigned)yy >= (unsigned)H) continue;
      for (int xx=x-1; xx<=x+1; xx++){
        if ((unsigned)xx >= (unsigned)W) continue;
        float ev = e[yy*W+xx];
        den = __fadd_rn(den, ev);
        if (dd != d) sd = __fadd_rn(sd, __fmul_rn(ev, (float)(dd-d)));
        if (xx != x) sx = __fadd_rn(sx, __fmul_rn(ev, (float)(xx-x)));
        if (yy != y) sy = __fadd_rn(sy, __fmul_rn(ev, (float)(yy-y)));
      }
    }
  }
  float dE = __fadd_rn(den, EPSF);
  float cd = __fadd_rn(__fdiv_rn(sd,dE), (float)d);
  float cx = __fadd_rn(__fdiv_rn(sx,dE), (float)x);
  float cy = __fadd_rn(__fdiv_rn(sy,dE), (float)y);
  float scale = __fmul_rn(1.6f, (float)exp2((double)__fdiv_rn(cd, 3.0f)));
  float s6 = __fmul_rn(6.0f, scale);
  float g = ((__fsub_rn(cx,s6) > 0.f) && (__fadd_rn(cx,s6) < (float)(W-1)) &&
             (__fsub_rn(cy,s6) > 0.f) && (__fadd_rn(cy,s6) < (float)(H-1))) ? 1.f : 0.f;
  float mn = (float)(H < W ? H : W);
  int o = base + j;
  g_cand_resp[b][o] = __fmul_rn(v, g);
  float* Lf = g_cand_laf[b][o];
  Lf[0] = __fdiv_rn(s6,mn); Lf[1] = 0.f; Lf[2] = __fdiv_rn(cx,(float)W);
  Lf[3] = 0.f;              Lf[4] = __fdiv_rn(s6,mn); Lf[5] = __fdiv_rn(cy,(float)H);
}

__global__ void k_out(float* __restrict__ out){
  int t = blockIdx.x*blockDim.x + threadIdx.x;
  if (t >= 2*NFEAT) return;
  int b = t/NFEAT, j = t-b*NFEAT;
  unsigned i = g_finidx[b][j];
  const float* L = g_cand_laf[b][i];
  float* o = out + (b*NFEAT + j)*6;
  #pragma unroll
  for (int e=0;e<6;e++) o[e] = __fmul_rn(L[e], 1024.0f);
  out[2*NFEAT*6 + b*NFEAT + j] = g_finval[b][j];
}

// ---------------- host ----------------
static void launch_blurv(const float* src, float* dst, int S, const KW& kw, int n){
  dim3 g((S+127)/128, S/2, 2);
  switch(n){
    case 9:  k_blurv_t<9 ><<<g,128>>>(src,dst,S,S,kw); break;
    case 11: k_blurv_t<11><<<g,128>>>(src,dst,S,S,kw); break;
    case 13: k_blurv_t<13><<<g,128>>>(src,dst,S,S,kw); break;
    case 15: k_blurv_t<15><<<g,128>>>(src,dst,S,S,kw); break;
    case 17: k_blurv_t<17><<<g,128>>>(src,dst,S,S,kw); break;
    case 19: k_blurv_t<19><<<g,128>>>(src,dst,S,S,kw); break;
    case 21: k_blurv_t<21><<<g,128>>>(src,dst,S,S,kw); break;
    default: k_blurv_t<23><<<g,128>>>(src,dst,S,S,kw); break;
  }
}
static void launch_blurh(const float* src, float* dst, int S, const KW& kw, int n){
  dim3 g((S+127)/128, S/2, 2);
  switch(n){
    case 9:  k_blurh_t<9 ><<<g,128>>>(src,dst,S,S,kw); break;
    case 11: k_blurh_t<11><<<g,128>>>(src,dst,S,S,kw); break;
    case 13: k_blurh_t<13><<<g,128>>>(src,dst,S,S,kw); break;
    case 15: k_blurh_t<15><<<g,128>>>(src,dst,S,S,kw); break;
    case 17: k_blurh_t<17><<<g,128>>>(src,dst,S,S,kw); break;
    case 19: k_blurh_t<19><<<g,128>>>(src,dst,S,S,kw); break;
    case 21: k_blurh_t<21><<<g,128>>>(src,dst,S,S,kw); break;
    default: k_blurh_t<23><<<g,128>>>(src,dst,S,S,kw); break;
  }
}

extern "C" void kernel_launch(void* const* d_in, const int* in_sizes, int n_in,
                              void* d_out, int out_size){
  (void)in_sizes; (void)n_in; (void)out_size;
  const float* img = (const float*)d_in[0];
  float* out = (float*)d_out;

  float *p_lv = 0, *p_tmp = 0;
  cudaGetSymbolAddress((void**)&p_lv, g_lv);
  cudaGetSymbolAddress((void**)&p_tmp, g_tmp);

  double step = pow(2.0, 1.0/3.0);
  double q = sqrt(step*step - 1.0);
  double sgm[5]; int ksz[5];
  sgm[0] = sqrt(1.6*1.6 - 0.25);
  { double cs = 1.6; for (int i=1;i<5;i++){ sgm[i] = cs * q; cs *= step; } }
  for (int i=0;i<5;i++){ int k=(int)(8.0*sgm[i]+1.0); if(!(k&1))k++; ksz[i]=k; }
  float s4[5];
  { double cs = 1.6;
    for (int l=0;l<5;l++){ float sgf=(float)cs; s4[l]=powf(sgf,4.0f); cs*=step; } }

  // host weight pipeline: identical f32 op sequence (volatile blocks reassociation)
  KW kws[5];
  for (int t=0;t<5;t++){
    int n = ksz[t], h = n/2;
    volatile float den2 = (float)(2.0*sgm[t]*sgm[t]);
    float w[32];
    for (int i=0;i<n;i++){
      volatile float x = (float)(i - h);
      volatile float arg = -(x*x)/den2;
      w[i] = (float)exp((double)arg);
    }
    volatile float r[8];
    for (int j=0;j<8;j++) r[j] = w[j];
    int i = 8;
    for (; i + 8 <= n; i += 8)
      for (int j=0;j<8;j++) r[j] = r[j] + w[i+j];
    volatile float s01 = r[0]+r[1], s23 = r[2]+r[3], s45 = r[4]+r[5], s67 = r[6]+r[7];
    volatile float s0123 = s01+s23, s4567 = s45+s67;
    volatile float sum = s0123 + s4567;
    for (; i < n; i++) sum = sum + w[i];
    for (int k2=0;k2<24;k2++) kws[t].w[k2] = 0.f;
    for (int k2=0;k2<n;k2++) kws[t].w[k2] = w[k2]/sum;
  }

  static const int SS[7] = {1024,512,256,128,64,32,16};
  int base = 0;
  for (int o=0;o<7;o++){
    int S = SS[o], HW = S*S, tot = 2*HW;
    if (o == 0){
      launch_blurv(img, p_tmp, S, kws[0], ksz[0]);
      launch_blurh(p_tmp, p_lv, S, kws[0], ksz[0]);
    } else {
      int thr = 256, blk = (tot+thr-1)/thr;
      k_down<<<blk,thr>>>(S);
    }
    for (int i=1;i<5;i++){
      launch_blurv(p_lv+(i-1)*LVS, p_tmp, S, kws[i], ksz[i]);
      launch_blurh(p_tmp, p_lv+i*LVS, S, kws[i], ksz[i]);
    }
    dim3 tg((S+BX-1)/BX, (S+BY-1)/BY, 10);
    dim3 tb(BX, BY);
    k_hess2<<<tg,tb>>>(S,S,s4[0],s4[1],s4[2],s4[3],s4[4]);
    k_emap2<<<tg,tb>>>(S,S);
    k_tkinit<<<1,256>>>();           // zero bins BEFORE fused hist in vals
    k_vals2<<<tg,tb>>>(S,S);

    int N = 5*HW;
    if (N > NFEAT){
      int hb = (N+255)/256; if (hb > 2048) hb = 2048;
      k_compact1<<<dim3(hb,2),256>>>(N,HW);     // self round-0 scan + compact
      k_tail<<<2,1024>>>(HW);                   // rounds 1-3 + final compact
      k_sortsel<<<2,512>>>(0,HW,0);
      k_laf<<<dim3((NFEAT+127)/128,2),128>>>(S,S,NFEAT,1,base);
      base += NFEAT;
    } else {
      k_laf<<<dim3((N+127)/128,2),128>>>(S,S,N,0,base);
      base += N;
    }
  }

  // final selection over all candidates (base == 13280), fully fused
  k_tailf<<<2,1024>>>(base);
  k_sortsel<<<2,512>>>(1,0,1);
  k_out<<<(2*NFEAT+255)/256,256>>>(out);
}